// round 13
// baseline (speedup 1.0000x reference)
#include <cuda_runtime.h>
#include <cuda_fp16.h>

#define N_NODES 50000
#define N_EDGES 800000
#define HEADS 3
#define HC 192
#define NEG_SLOPE 0.2f
#define NTILES 49   // ceil(50000/1024)
#define CSR_BLOCKS 49

// ---------------- scratch ------------------------------------------------------
__device__ __half  g_xh[N_NODES * HC];       // x @ W_node (fp16, message path)
__device__ __half  g_E[(size_t)N_EDGES * HC];// e_ij rows (fp16) in CSR order
__device__ float4  g_w4[N_EDGES];            // exp(leaky(alpha)) per head, CSR order
__device__ float   g_sn[N_NODES * 8];        // [0..2]=s0(h), [4..6]=s2(h)
__device__ float   g_q[64];                  // folded edge-att vector (48 used)
__device__ float   g_v[6 * 64];              // folded node-att vectors v0/v2
__device__ int     g_srcs[N_EDGES];          // CSR: src node
__device__ int     g_pos[N_EDGES];           // edge id -> CSR position
__device__ int     g_deg[N_NODES];
__device__ int     g_rowptr[N_NODES + 1];
__device__ int     g_cursor[N_NODES];
__device__ int     g_tsum[64], g_toff[64];
__device__ int     g_bcnt[4], g_brel[4];     // grid-barrier state (reset by k_init)
__device__ float   g_aggr[N_NODES * HC];

// ---------------- f32x2 helpers -------------------------------------------------
__device__ __forceinline__ unsigned long long pk2(float lo, float hi) {
    unsigned long long r;
    asm("mov.b64 %0, {%1,%2};" : "=l"(r) : "f"(lo), "f"(hi));
    return r;
}
__device__ __forceinline__ void fma2(unsigned long long& d,
                                     unsigned long long a,
                                     unsigned long long b) {
    asm("fma.rn.f32x2 %0, %1, %2, %0;" : "+l"(d) : "l"(a), "l"(b));
}
__device__ __forceinline__ void unpk2(float& lo, float& hi, unsigned long long v) {
    asm("mov.b64 {%0,%1}, %2;" : "=f"(lo), "=f"(hi) : "l"(v));
}

// ---------------- grid barrier (49 co-resident blocks; one-shot per slot) -------
__device__ __forceinline__ void gbar(int b) {
    __syncthreads();
    if (threadIdx.x == 0) {
        __threadfence();
        if (atomicAdd(&g_bcnt[b], 1) == CSR_BLOCKS - 1) {
            atomicExch(&g_brel[b], 1);
        } else {
            while (atomicAdd(&g_brel[b], 0) == 0) __nanosleep(64);
        }
        __threadfence();
    }
    __syncthreads();
}

// ---------------- K1: zero deg + fold att vectors + reset barriers ---------------
__global__ void k_init(const float* __restrict__ Wn, const float* __restrict__ We,
                       const float* __restrict__ att) {
    int b = blockIdx.x, t = threadIdx.x;
    if (b < 49) {
        int i = b * 1024 + t;
        if (i < N_NODES) g_deg[i] = 0;
        return;
    }
    if (t < 4) { g_bcnt[t] = 0; g_brel[t] = 0; }
    if (t < 48) {
        int h = t >> 4, k = t & 15;
        float s = 0.f;
        const float* wr = We + k * HC + h * 64;
        const float* ar = att + h * HC + 64;
#pragma unroll 8
        for (int c = 0; c < 64; c++) s += wr[c] * ar[c];
        g_q[t] = s;
    } else if (t < 48 + 384) {
        int o2 = t - 48;
        int o = o2 >> 6, k = o2 & 63;
        int type = (o >= 3), h = (o >= 3) ? o - 3 : o;
        float s = 0.f;
        const float* wr = Wn + k * HC + h * 64;
        const float* ar = att + h * HC + type * 128;
#pragma unroll 8
        for (int c = 0; c < 64; c++) s += wr[c] * ar[c];
        g_v[o * 64 + k] = s;
    }
}

// ---------------- K2: x_proj (fp16) + shuffle-free s0/s2 ------------------------
__global__ void k_projs(const float* __restrict__ x, const float* __restrict__ Wn) {
    __shared__ __align__(16) float xT[64 * 8];  // [k][n]
    __shared__ float s_v[6 * 65];
    int n0 = blockIdx.x * 8;
    int t = threadIdx.x;                 // 0..95
    int ch0 = t, ch1 = t + 96;
    for (int i = t; i < 8 * 64; i += 96) {
        int n = i >> 6, k = i & 63;
        xT[k * 8 + n] = x[(n0 + n) * 64 + k];
    }
    for (int i = t; i < 384; i += 96) {
        int o = i >> 6, k = i & 63;
        s_v[o * 65 + k] = g_v[i];
    }
    __syncthreads();
    unsigned long long accA2[4], accB2[4];
#pragma unroll
    for (int p = 0; p < 4; p++) { accA2[p] = 0ull; accB2[p] = 0ull; }
#pragma unroll 4
    for (int k = 0; k < 64; k++) {
        float wa = Wn[k * HC + ch0];
        float wb = Wn[k * HC + ch1];
        unsigned long long wa2 = pk2(wa, wa), wb2 = pk2(wb, wb);
        const ulonglong2* xr = reinterpret_cast<const ulonglong2*>(xT + k * 8);
        ulonglong2 x01 = xr[0], x23 = xr[1];
        fma2(accA2[0], x01.x, wa2); fma2(accA2[1], x01.y, wa2);
        fma2(accA2[2], x23.x, wa2); fma2(accA2[3], x23.y, wa2);
        fma2(accB2[0], x01.x, wb2); fma2(accB2[1], x01.y, wb2);
        fma2(accB2[2], x23.x, wb2); fma2(accB2[3], x23.y, wb2);
    }
    float accA[8], accB[8];
#pragma unroll
    for (int p = 0; p < 4; p++) {
        unpk2(accA[2 * p], accA[2 * p + 1], accA2[p]);
        unpk2(accB[2 * p], accB[2 * p + 1], accB2[p]);
    }
#pragma unroll
    for (int n = 0; n < 8; n++) {
        g_xh[(n0 + n) * HC + ch0] = __float2half(accA[n]);
        g_xh[(n0 + n) * HC + ch1] = __float2half(accB[n]);
    }
    if (t < 48) {
        int n = t & 7, o = t >> 3;
        int type = (o >= 3), h = (o >= 3) ? o - 3 : o;
        const float* vv = s_v + o * 65;
        float s = 0.f;
#pragma unroll 8
        for (int k = 0; k < 64; k++) s += xT[k * 8 + n] * vv[k];
        g_sn[(n0 + n) * 8 + type * 4 + h] = s;
    }
}

// ---------------- K3: full CSR build in one kernel (49 blocks, grid barriers) ---
__global__ void __launch_bounds__(1024) k_csr(const int* __restrict__ ei) {
    int b = blockIdx.x, t = threadIdx.x, w = t >> 5, lane = t & 31;

    for (int e = b * 1024 + t; e < N_EDGES; e += CSR_BLOCKS * 1024)
        atomicAdd(&g_deg[ei[N_EDGES + e]], 1);
    gbar(0);

    {
        __shared__ int s_ws[32], s_off[32];
        int i = b * 1024 + t;
        int v = (i < N_NODES) ? g_deg[i] : 0;
        int incl = v;
#pragma unroll
        for (int o = 1; o < 32; o <<= 1) {
            int u = __shfl_up_sync(0xffffffffu, incl, o);
            if (lane >= o) incl += u;
        }
        if (lane == 31) s_ws[w] = incl;
        __syncthreads();
        if (w == 0) {
            int wv = s_ws[lane];
            int inc2 = wv;
#pragma unroll
            for (int o = 1; o < 32; o <<= 1) {
                int u = __shfl_up_sync(0xffffffffu, inc2, o);
                if (lane >= o) inc2 += u;
            }
            s_off[lane] = inc2 - wv;
            if (lane == 31) g_tsum[b] = inc2;
        }
        __syncthreads();
        if (i < N_NODES) g_rowptr[i] = s_off[w] + incl - v;
    }
    gbar(1);

    if (b == 0) {
        __shared__ int s2[64];
        int v = (t < NTILES) ? g_tsum[t] : 0;
        if (t < 64) s2[t] = v;
        __syncthreads();
#pragma unroll
        for (int o = 1; o < 64; o <<= 1) {
            int add = (t >= o && t < 64) ? s2[t - o] : 0;
            __syncthreads();
            if (t < 64) s2[t] += add;
            __syncthreads();
        }
        if (t < NTILES) g_toff[t] = s2[t] - v;
        if (t == NTILES - 1) g_rowptr[N_NODES] = s2[t];
    }
    gbar(2);

    {
        int i = b * 1024 + t;
        if (i < N_NODES) {
            int v = g_rowptr[i] + g_toff[b];
            g_rowptr[i] = v;
            g_cursor[i] = v;
        }
    }
    gbar(3);

    for (int e = b * 1024 + t; e < N_EDGES; e += CSR_BLOCKS * 1024) {
        int src = ei[e];
        int dst = ei[N_EDGES + e];
        int pos = atomicAdd(&g_cursor[dst], 1);
        g_srcs[pos] = src;
        g_pos[e] = pos;
    }
}

// ---------------- K4 (PROFILED): E = eattr @ We (fp16, CSR order) + alpha -------
// 96 threads, 8 edges/block. f32x2 pairs over edges; alpha on warp 0.
__global__ void __launch_bounds__(96) k_egemm(const int* __restrict__ ei,
                                              const float* __restrict__ eattr,
                                              const float* __restrict__ We) {
    __shared__ __align__(16) float s_a[16][8];   // eattr transposed [k][e]
    __shared__ float qs[48];
    __shared__ int   s_pos[8];
    __shared__ __align__(16) float4 s_sd[8], s_ss[8];
    __shared__ float s_wv[8][4];
    int t = threadIdx.x;
    int e0 = blockIdx.x * 8;

    for (int i = t; i < 128; i += 96) {
        int e = i >> 4, k = i & 15;
        s_a[k][e] = eattr[(size_t)(e0 + e) * 16 + k];
    }
    if (t < 48) qs[t] = g_q[t];
    if (t < 8) {
        s_pos[t] = g_pos[e0 + t];
        int src = ei[e0 + t], dst = ei[N_EDGES + e0 + t];
        s_sd[t] = *reinterpret_cast<const float4*>(g_sn + (size_t)dst * 8);
        s_ss[t] = *reinterpret_cast<const float4*>(g_sn + (size_t)src * 8 + 4);
    }
    __syncthreads();

    // GEMM: thread t owns channels (2t, 2t+1) for all 8 edges
    unsigned long long acc[8];
#pragma unroll
    for (int p = 0; p < 8; p++) acc[p] = 0ull;
#pragma unroll
    for (int k = 0; k < 16; k++) {
        float2 w = *reinterpret_cast<const float2*>(We + k * HC + 2 * t);
        unsigned long long w0 = pk2(w.x, w.x), w1 = pk2(w.y, w.y);
        const ulonglong2* ar = reinterpret_cast<const ulonglong2*>(&s_a[k][0]);
        ulonglong2 a01 = ar[0], a23 = ar[1];
        fma2(acc[0], a01.x, w0); fma2(acc[1], a01.y, w0);
        fma2(acc[2], a23.x, w0); fma2(acc[3], a23.y, w0);
        fma2(acc[4], a01.x, w1); fma2(acc[5], a01.y, w1);
        fma2(acc[6], a23.x, w1); fma2(acc[7], a23.y, w1);
    }

    // alpha: 24 units (8 edges x 3 heads) on warp 0
    if (t < 32 && (t & 3) < 3) {
        int el = t >> 2, h = t & 3;
        const float* q = qs + h * 16;
        float s = reinterpret_cast<const float*>(&s_sd[el])[h]
                + reinterpret_cast<const float*>(&s_ss[el])[h];
#pragma unroll
        for (int k = 0; k < 16; k++) s += s_a[k][el] * q[k];
        s = (s >= 0.f) ? s : NEG_SLOPE * s;
        s_wv[el][h] = __expf(s);
    }
    __syncthreads();

    // write E rows (fp16 half2 per thread) at CSR positions
#pragma unroll
    for (int p = 0; p < 4; p++) {
        float a0, b0, a1, b1;
        unpk2(a0, b0, acc[p]);       // channel 2t for edges 2p, 2p+1
        unpk2(a1, b1, acc[p + 4]);   // channel 2t+1
        *reinterpret_cast<__half2*>(g_E + (size_t)s_pos[2 * p] * HC + 2 * t) =
            __floats2half2_rn(a0, a1);
        *reinterpret_cast<__half2*>(g_E + (size_t)s_pos[2 * p + 1] * HC + 2 * t) =
            __floats2half2_rn(b0, b1);
    }
    if (t < 8)
        g_w4[s_pos[t]] = make_float4(s_wv[t][0], s_wv[t][1], s_wv[t][2], 0.f);
}

// ---------------- K5: per-node weighted gather-reduce ----------------------------
// One node per block, 96 threads: thread t owns channels (2t, 2t+1); h = t>>5.
#define CHUNK 32
__global__ void __launch_bounds__(96) k_aggr() {
    int t = threadIdx.x;
    int c0 = 2 * t;
    int h = t >> 5;
    __shared__ __align__(16) float4 s_w4[CHUNK];
    __shared__ int s_src[CHUNK];

    int i = blockIdx.x;
    int rs = g_rowptr[i], re = g_rowptr[i + 1];
    float z = 0.f, acc0 = 0.f, acc1 = 0.f;

    for (int base = rs; base < re; base += CHUNK) {
        int Cn = min(CHUNK, re - base);
        if (t < Cn) {
            s_w4[t] = g_w4[base + t];
            s_src[t] = g_srcs[base + t];
        }
        __syncthreads();
        __half2 E2 = *reinterpret_cast<const __half2*>(
            g_E + (size_t)base * HC + c0);
        __half2 xh = *reinterpret_cast<const __half2*>(
            g_xh + (size_t)s_src[0] * HC + c0);
        for (int j = 0; j < Cn; j++) {
            __half2 E2n, xhn;
            if (j + 1 < Cn) {
                E2n = *reinterpret_cast<const __half2*>(
                    g_E + (size_t)(base + j + 1) * HC + c0);
                xhn = *reinterpret_cast<const __half2*>(
                    g_xh + (size_t)s_src[j + 1] * HC + c0);
            }
            float2 e = __half22float2(E2);
            float2 x = __half22float2(xh);
            float w = reinterpret_cast<const float*>(&s_w4[j])[h];
            z += w;
            acc0 = fmaf(w * x.x, e.x, acc0);
            acc1 = fmaf(w * x.y, e.y, acc1);
            E2 = E2n; xh = xhn;
        }
        __syncthreads();
    }
    float inv = 1.f / (z + 1e-16f);
    *reinterpret_cast<float2*>(g_aggr + (size_t)i * HC + c0) =
        make_float2(acc0 * inv, acc1 * inv);
}

// ---------------- K6: out = aggr @ W_scale + bias ---------------------------------
__global__ void k_out(const float* __restrict__ Ws, const float* __restrict__ bias,
                      float* __restrict__ out) {
    __shared__ __align__(16) float aT[HC * 8];
    int n0 = blockIdx.x * 8;
    int t = threadIdx.x;  // 0..63
    for (int i = t; i < 8 * HC; i += 64) {
        int n = i / HC, k = i - n * HC;
        aT[k * 8 + n] = g_aggr[(n0 + n) * HC + k];
    }
    __syncthreads();
    unsigned long long acc2[4];
#pragma unroll
    for (int p = 0; p < 4; p++) acc2[p] = 0ull;
#pragma unroll 4
    for (int k = 0; k < HC; k++) {
        unsigned long long wv2 = pk2(Ws[k * 64 + t], Ws[k * 64 + t]);
        const ulonglong2* ar = reinterpret_cast<const ulonglong2*>(aT + k * 8);
        ulonglong2 v01 = ar[0], v23 = ar[1];
        fma2(acc2[0], v01.x, wv2); fma2(acc2[1], v01.y, wv2);
        fma2(acc2[2], v23.x, wv2); fma2(acc2[3], v23.y, wv2);
    }
    float acc[8];
#pragma unroll
    for (int p = 0; p < 4; p++) unpk2(acc[2 * p], acc[2 * p + 1], acc2[p]);
    float b = bias[t];
#pragma unroll
    for (int n = 0; n < 8; n++) out[(n0 + n) * 64 + t] = acc[n] + b;
}

// ---------------- launch ----------------------------------------------------------
extern "C" void kernel_launch(void* const* d_in, const int* in_sizes, int n_in,
                              void* d_out, int out_size) {
    const float* x     = (const float*)d_in[0];
    const int*   ei    = (const int*)d_in[1];
    const float* eattr = (const float*)d_in[2];
    const float* Wn    = (const float*)d_in[3];
    const float* We    = (const float*)d_in[4];
    const float* att   = (const float*)d_in[5];
    const float* Ws    = (const float*)d_in[6];
    const float* bias  = (const float*)d_in[7];
    float*       out   = (float*)d_out;

    k_init<<<50, 1024>>>(Wn, We, att);
    k_projs<<<N_NODES / 8, 96>>>(x, Wn);
    k_csr<<<CSR_BLOCKS, 1024>>>(ei);
    k_egemm<<<N_EDGES / 8, 96>>>(ei, eattr, We);   // 4th launch -> profiled
    k_aggr<<<N_NODES, 96>>>();
    k_out<<<N_NODES / 8, 64>>>(Ws, bias, out);
}

// round 16
// speedup vs baseline: 1.1806x; 1.1806x over previous
#include <cuda_runtime.h>
#include <cuda_fp16.h>

#define N_NODES 50000
#define N_EDGES 800000
#define HEADS 3
#define HC 192
#define NEG_SLOPE 0.2f
#define NTILES 49   // ceil(50000/1024)

// ---------------- scratch ------------------------------------------------------
__device__ __half  g_xh[N_NODES * HC];       // x @ W_node (fp16)
__device__ float   g_sn[N_NODES * 8];        // [0..2]=s0(h), [4..6]=s2(h)
__device__ float   g_q[64];                  // folded edge-att vector (48 used)
__device__ float   g_v[6 * 64];              // folded node-att vectors v0/v2
__device__ unsigned g_wbh[3 * 8 * 2 * 32];   // We mma B-fragments (fp16x2)
__device__ int2    g_se[N_EDGES];            // CSR: (src, eid)
__device__ int     g_deg[N_NODES];
__device__ int     g_rowptr[N_NODES + 1];
__device__ int     g_cursor[N_NODES];
__device__ int     g_tsum[64], g_toff[64];
__device__ float   g_aggr[N_NODES * HC];

// ---------------- helpers --------------------------------------------------------
__device__ __forceinline__ unsigned long long pk2(float lo, float hi) {
    unsigned long long r;
    asm("mov.b64 %0, {%1,%2};" : "=l"(r) : "f"(lo), "f"(hi));
    return r;
}
__device__ __forceinline__ void fma2(unsigned long long& d,
                                     unsigned long long a,
                                     unsigned long long b) {
    asm("fma.rn.f32x2 %0, %1, %2, %0;" : "+l"(d) : "l"(a), "l"(b));
}
__device__ __forceinline__ void unpk2(float& lo, float& hi, unsigned long long v) {
    asm("mov.b64 {%0,%1}, %2;" : "=f"(lo), "=f"(hi) : "l"(v));
}
__device__ __forceinline__ unsigned h2u(float a, float b) {
    __half2 h = __floats2half2_rn(a, b);
    return *reinterpret_cast<unsigned*>(&h);
}

// ---------------- K: zero degree histogram --------------------------------------
__global__ void k_zero() {
    int i = blockIdx.x * blockDim.x + threadIdx.x;
    if (i < N_NODES) g_deg[i] = 0;
}

// ---------------- K: degree histogram -------------------------------------------
__global__ void k_deg(const int* __restrict__ ei) {
    int e = blockIdx.x * blockDim.x + threadIdx.x;
    if (e < N_EDGES) atomicAdd(&g_deg[ei[N_EDGES + e]], 1);
}

// ---------------- K: fold attention vectors + build mma B-fragments -------------
__global__ void k_fold(const float* __restrict__ Wn, const float* __restrict__ We,
                       const float* __restrict__ att) {
    int t = threadIdx.x;   // 512 threads
    if (t < 48) {
        int h = t >> 4, k = t & 15;
        float s = 0.f;
        const float* wr = We + k * HC + h * 64;
        const float* ar = att + h * HC + 64;
#pragma unroll 8
        for (int c = 0; c < 64; c++) s += wr[c] * ar[c];
        g_q[t] = s;
    } else if (t < 48 + 384) {
        int o2 = t - 48;
        int o = o2 >> 6, k = o2 & 63;
        int type = (o >= 3), h = (o >= 3) ? o - 3 : o;
        float s = 0.f;
        const float* wr = Wn + k * HC + h * 64;
        const float* ar = att + h * HC + type * 128;
#pragma unroll 8
        for (int c = 0; c < 64; c++) s += wr[c] * ar[c];
        g_v[o * 64 + k] = s;
    }
    // B fragments for mma.m16n8k16 (B col-major k x n):
    //  reg r holds half2( We[k0][n], We[k0+1][n] ), k0 = (lane%4)*2 + r*8,
    //  n = h*64 + nt*8 + lane/4
    for (int idx = t; idx < 3 * 8 * 2 * 32; idx += 512) {
        int lane = idx & 31;
        int reg = (idx >> 5) & 1;
        int nt = (idx >> 6) & 7;
        int h = idx >> 9;
        int k0 = (lane & 3) * 2 + reg * 8;
        int n = h * 64 + nt * 8 + (lane >> 2);
        g_wbh[idx] = h2u(We[k0 * HC + n], We[(k0 + 1) * HC + n]);
    }
}

// ---------------- K: x_proj (fp16) + shuffle-free s0/s2 ------------------------
__global__ void k_projs(const float* __restrict__ x, const float* __restrict__ Wn) {
    __shared__ __align__(16) float xT[64 * 8];  // [k][n]
    __shared__ float s_v[6 * 65];
    int n0 = blockIdx.x * 8;
    int t = threadIdx.x;                 // 0..95
    int ch0 = t, ch1 = t + 96;
    for (int i = t; i < 8 * 64; i += 96) {
        int n = i >> 6, k = i & 63;
        xT[k * 8 + n] = x[(n0 + n) * 64 + k];
    }
    for (int i = t; i < 384; i += 96) {
        int o = i >> 6, k = i & 63;
        s_v[o * 65 + k] = g_v[i];
    }
    __syncthreads();
    unsigned long long accA2[4], accB2[4];
#pragma unroll
    for (int p = 0; p < 4; p++) { accA2[p] = 0ull; accB2[p] = 0ull; }
#pragma unroll 4
    for (int k = 0; k < 64; k++) {
        float wa = Wn[k * HC + ch0];
        float wb = Wn[k * HC + ch1];
        unsigned long long wa2 = pk2(wa, wa), wb2 = pk2(wb, wb);
        const ulonglong2* xr = reinterpret_cast<const ulonglong2*>(xT + k * 8);
        ulonglong2 x01 = xr[0], x23 = xr[1];
        fma2(accA2[0], x01.x, wa2); fma2(accA2[1], x01.y, wa2);
        fma2(accA2[2], x23.x, wa2); fma2(accA2[3], x23.y, wa2);
        fma2(accB2[0], x01.x, wb2); fma2(accB2[1], x01.y, wb2);
        fma2(accB2[2], x23.x, wb2); fma2(accB2[3], x23.y, wb2);
    }
    float accA[8], accB[8];
#pragma unroll
    for (int p = 0; p < 4; p++) {
        unpk2(accA[2 * p], accA[2 * p + 1], accA2[p]);
        unpk2(accB[2 * p], accB[2 * p + 1], accB2[p]);
    }
#pragma unroll
    for (int n = 0; n < 8; n++) {
        g_xh[(n0 + n) * HC + ch0] = __float2half(accA[n]);
        g_xh[(n0 + n) * HC + ch1] = __float2half(accB[n]);
    }
    if (t < 48) {
        int n = t & 7, o = t >> 3;
        int type = (o >= 3), h = (o >= 3) ? o - 3 : o;
        const float* vv = s_v + o * 65;
        float s = 0.f;
#pragma unroll 8
        for (int k = 0; k < 64; k++) s += xT[k * 8 + n] * vv[k];
        g_sn[(n0 + n) * 8 + type * 4 + h] = s;
    }
}

// ---------------- K: scan phase 1 ------------------------------------------------
__global__ void k_scan1() {
    __shared__ int s_ws[32], s_off[32];
    int t = threadIdx.x, w = t >> 5, lane = t & 31;
    int i = blockIdx.x * 1024 + t;
    int v = (i < N_NODES) ? g_deg[i] : 0;
    int incl = v;
#pragma unroll
    for (int o = 1; o < 32; o <<= 1) {
        int u = __shfl_up_sync(0xffffffffu, incl, o);
        if (lane >= o) incl += u;
    }
    if (lane == 31) s_ws[w] = incl;
    __syncthreads();
    if (w == 0) {
        int wv = s_ws[lane];
        int inc2 = wv;
#pragma unroll
        for (int o = 1; o < 32; o <<= 1) {
            int u = __shfl_up_sync(0xffffffffu, inc2, o);
            if (lane >= o) inc2 += u;
        }
        s_off[lane] = inc2 - wv;
        if (lane == 31) g_tsum[blockIdx.x] = inc2;
    }
    __syncthreads();
    if (i < N_NODES) g_rowptr[i] = s_off[w] + incl - v;
}

// ---------------- K: scan phase 2 -------------------------------------------------
__global__ void k_scan2() {
    __shared__ int s[64];
    int t = threadIdx.x;
    int v = (t < NTILES) ? g_tsum[t] : 0;
    s[t] = v;
    __syncthreads();
#pragma unroll
    for (int o = 1; o < 64; o <<= 1) {
        int add = (t >= o) ? s[t - o] : 0;
        __syncthreads();
        s[t] += add;
        __syncthreads();
    }
    if (t < NTILES) g_toff[t] = s[t] - v;
    if (t == NTILES - 1) g_rowptr[N_NODES] = s[t];
}

// ---------------- K: scan phase 3 -------------------------------------------------
__global__ void k_scan3() {
    int i = blockIdx.x * 1024 + threadIdx.x;
    if (i < N_NODES) {
        int v = g_rowptr[i] + g_toff[blockIdx.x];
        g_rowptr[i] = v;
        g_cursor[i] = v;
    }
}

// ---------------- K: light CSR scatter of (src, eid) ------------------------------
__global__ void k_scatter(const int* __restrict__ ei) {
    int e = blockIdx.x * blockDim.x + threadIdx.x;
    if (e >= N_EDGES) return;
    int src = ei[e];
    int dst = ei[N_EDGES + e];
    int pos = atomicAdd(&g_cursor[dst], 1);
    g_se[pos] = make_int2(src, e);
}

// ---------------- K: per-node aggregation with HMMA e_ij -------------------------
// One node per 96-thread block; warp h owns head h (64 channels) independently.
#define CH 16
__global__ void __launch_bounds__(96) k_aggr(const float* __restrict__ eattr) {
    int t = threadIdx.x, lane = t & 31, h = t >> 5;
    int lg = lane >> 2;   // mma row group
    int lq = lane & 3;    // mma col group

    __shared__ __align__(16) unsigned s_ea[3][CH * 8];  // fp16 ea rows
    __shared__ unsigned s_x[3][CH][36];       // fp16 xh (64 ch = 32 u32), pad 36
    __shared__ float    s_w[3][CH];
    __shared__ float    qs[48];
    if (t < 48) qs[t] = g_q[t];
    __syncthreads();

    // B fragments (per warp: 8 n-tiles x 2 regs)
    unsigned B0[8], B1[8];
#pragma unroll
    for (int nt = 0; nt < 8; nt++) {
        B0[nt] = g_wbh[((h * 8 + nt) * 2 + 0) * 32 + lane];
        B1[nt] = g_wbh[((h * 8 + nt) * 2 + 1) * 32 + lane];
    }

    int i = blockIdx.x;
    int rs = g_rowptr[i], re = g_rowptr[i + 1];
    float sb = g_sn[(size_t)i * 8 + h];
    float z = 0.f;
    float accx[8], accy[8];
#pragma unroll
    for (int nt = 0; nt < 8; nt++) { accx[nt] = 0.f; accy[nt] = 0.f; }

    const unsigned* xh32 = reinterpret_cast<const unsigned*>(g_xh);

    for (int base = rs; base < re; base += CH) {
        int Cn = min(CH, re - base);
        int mysrc = 0, myeid = 0;
        if (lane < Cn) {
            int2 se = g_se[base + lane];
            mysrc = se.x; myeid = se.y;
        }
        // stage ea (fp16): lane covers (edge = lane>>1, half-row = lane&1).
        // shfl executed by ALL lanes (uniform control flow) — divergent-shfl fix.
        {
            int e2 = lane >> 1, hf = lane & 1;
            int eid = __shfl_sync(0xffffffffu, myeid, e2);  // garbage ok if e2>=Cn
            uint4 vv = make_uint4(0u, 0u, 0u, 0u);
            if (e2 < Cn) {
                const float4* ap =
                    reinterpret_cast<const float4*>(eattr) + (size_t)eid * 4 + hf * 2;
                float4 f0 = ap[0], f1 = ap[1];
                vv = make_uint4(h2u(f0.x, f0.y), h2u(f0.z, f0.w),
                                h2u(f1.x, f1.y), h2u(f1.z, f1.w));
            }
            *reinterpret_cast<uint4*>(&s_ea[h][e2 * 8 + hf * 4]) = vv;
        }
        // stage xh rows (64 ch fp16 = 32 u32/row; lane = u32 index)
#pragma unroll 4
        for (int j = 0; j < CH; j++) {
            unsigned v = 0u;
            if (j < Cn) {                    // uniform condition — safe shfl
                int sj = __shfl_sync(0xffffffffu, mysrc, j);
                v = xh32[(size_t)sj * 96 + h * 32 + lane];
            }
            s_x[h][j][lane] = v;
        }
        __syncwarp();

        // alpha for my head (lanes 0..CH-1) from fp32 eattr (L1-hot)
        if (lane < CH) {
            float wv = 0.f;
            if (lane < Cn) {
                float s = sb + g_sn[(size_t)mysrc * 8 + 4 + h];
                const float* q = qs + h * 16;
                const float4* ap =
                    reinterpret_cast<const float4*>(eattr) + (size_t)myeid * 4;
                float4 b0 = ap[0], b1 = ap[1], b2 = ap[2], b3 = ap[3];
                s += b0.x * q[0]  + b0.y * q[1]  + b0.z * q[2]  + b0.w * q[3];
                s += b1.x * q[4]  + b1.y * q[5]  + b1.z * q[6]  + b1.w * q[7];
                s += b2.x * q[8]  + b2.y * q[9]  + b2.z * q[10] + b2.w * q[11];
                s += b3.x * q[12] + b3.y * q[13] + b3.z * q[14] + b3.w * q[15];
                s = (s >= 0.f) ? s : NEG_SLOPE * s;
                wv = __expf(s);
            }
            s_w[h][lane] = wv;
        }
        // A fragments (m16k16, row-major)
        unsigned a0 = s_ea[h][lg * 8 + lq];
        unsigned a1 = s_ea[h][(lg + 8) * 8 + lq];
        unsigned a2 = s_ea[h][lg * 8 + 4 + lq];
        unsigned a3 = s_ea[h][(lg + 8) * 8 + 4 + lq];
        __syncwarp();

        // z accumulation (uniform across warp)
#pragma unroll
        for (int j = 0; j < CH; j += 4)
            z += s_w[h][j] + s_w[h][j + 1] + s_w[h][j + 2] + s_w[h][j + 3];

        float w_r  = s_w[h][lg];
        float w_r8 = s_w[h][lg + 8];
#pragma unroll
        for (int nt = 0; nt < 8; nt++) {
            float d0 = 0.f, d1 = 0.f, d2 = 0.f, d3 = 0.f;
            asm volatile(
                "mma.sync.aligned.m16n8k16.row.col.f32.f16.f16.f32 "
                "{%0,%1,%2,%3}, {%4,%5,%6,%7}, {%8,%9}, {%0,%1,%2,%3};"
                : "+f"(d0), "+f"(d1), "+f"(d2), "+f"(d3)
                : "r"(a0), "r"(a1), "r"(a2), "r"(a3), "r"(B0[nt]), "r"(B1[nt]));
            float2 xa = __half22float2(
                *reinterpret_cast<const __half2*>(&s_x[h][lg][nt * 4 + lq]));
            float2 xb = __half22float2(
                *reinterpret_cast<const __half2*>(&s_x[h][lg + 8][nt * 4 + lq]));
            accx[nt] = fmaf(w_r * xa.x, d0, accx[nt]);
            accy[nt] = fmaf(w_r * xa.y, d1, accy[nt]);
            accx[nt] = fmaf(w_r8 * xb.x, d2, accx[nt]);
            accy[nt] = fmaf(w_r8 * xb.y, d3, accy[nt]);
        }
        __syncwarp();
    }

    // reduce over the 8 row groups (lanes sharing lane%4)
#pragma unroll
    for (int nt = 0; nt < 8; nt++) {
#pragma unroll
        for (int o = 4; o <= 16; o <<= 1) {
            accx[nt] += __shfl_down_sync(0xffffffffu, accx[nt], o);
            accy[nt] += __shfl_down_sync(0xffffffffu, accy[nt], o);
        }
    }
    float inv = 1.f / (z + 1e-16f);
    if (lane < 4) {
#pragma unroll
        for (int nt = 0; nt < 8; nt++) {
            *reinterpret_cast<float2*>(
                g_aggr + (size_t)i * HC + h * 64 + nt * 8 + lane * 2) =
                make_float2(accx[nt] * inv, accy[nt] * inv);
        }
    }
}

// ---------------- K: out = aggr @ W_scale + bias ---------------------------------
__global__ void k_out(const float* __restrict__ Ws, const float* __restrict__ bias,
                      float* __restrict__ out) {
    __shared__ __align__(16) float aT[HC * 8];
    int n0 = blockIdx.x * 8;
    int t = threadIdx.x;  // 0..63
    for (int i = t; i < 8 * HC; i += 64) {
        int n = i / HC, k = i - n * HC;
        aT[k * 8 + n] = g_aggr[(n0 + n) * HC + k];
    }
    __syncthreads();
    unsigned long long acc2[4];
#pragma unroll
    for (int p = 0; p < 4; p++) acc2[p] = 0ull;
#pragma unroll 4
    for (int k = 0; k < HC; k++) {
        unsigned long long wv2 = pk2(Ws[k * 64 + t], Ws[k * 64 + t]);
        const ulonglong2* ar = reinterpret_cast<const ulonglong2*>(aT + k * 8);
        ulonglong2 v01 = ar[0], v23 = ar[1];
        fma2(acc2[0], v01.x, wv2); fma2(acc2[1], v01.y, wv2);
        fma2(acc2[2], v23.x, wv2); fma2(acc2[3], v23.y, wv2);
    }
    float acc[8];
#pragma unroll
    for (int p = 0; p < 4; p++) unpk2(acc[2 * p], acc[2 * p + 1], acc2[p]);
    float b = bias[t];
#pragma unroll
    for (int n = 0; n < 8; n++) out[(n0 + n) * 64 + t] = acc[n] + b;
}

// ---------------- launch ----------------------------------------------------------
extern "C" void kernel_launch(void* const* d_in, const int* in_sizes, int n_in,
                              void* d_out, int out_size) {
    const float* x     = (const float*)d_in[0];
    const int*   ei    = (const int*)d_in[1];
    const float* eattr = (const float*)d_in[2];
    const float* Wn    = (const float*)d_in[3];
    const float* We    = (const float*)d_in[4];
    const float* att   = (const float*)d_in[5];
    const float* Ws    = (const float*)d_in[6];
    const float* bias  = (const float*)d_in[7];
    float*       out   = (float*)d_out;

    k_zero<<<(N_NODES + 255) / 256, 256>>>();
    k_deg<<<(N_EDGES + 255) / 256, 256>>>(ei);
    k_fold<<<1, 512>>>(Wn, We, att);
    k_projs<<<N_NODES / 8, 96>>>(x, Wn);
    k_scan1<<<NTILES, 1024>>>();
    k_scan2<<<1, 64>>>();
    k_scan3<<<NTILES, 1024>>>();
    k_scatter<<<(N_EDGES + 255) / 256, 256>>>(ei);
    k_aggr<<<N_NODES, 96>>>(eattr);
    k_out<<<N_NODES / 8, 64>>>(Ws, bias, out);
}

// round 17
// speedup vs baseline: 1.3377x; 1.1331x over previous
#include <cuda_runtime.h>
#include <cuda_fp16.h>

#define N_NODES 50000
#define N_EDGES 800000
#define HEADS 3
#define HC 192
#define NEG_SLOPE 0.2f
#define NTILES 49   // ceil(50000/1024)

// ---------------- scratch ------------------------------------------------------
__device__ __half  g_xh[N_NODES * HC];       // x @ W_node (fp16, message path)
__device__ float   g_sn[N_NODES * 8];        // [0..2]=s0(h), [4..6]=s2(h)
__device__ float   g_q[64];                  // folded edge-att vector (48 used)
__device__ float   g_v[6 * 64];              // folded node-att vectors v0/v2
__device__ int2    g_se[N_EDGES];            // CSR: (src, eid)
__device__ int     g_deg[N_NODES];
__device__ int     g_rowptr[N_NODES + 1];
__device__ int     g_cursor[N_NODES];
__device__ int     g_tsum[64], g_toff[64];
__device__ float   g_aggr[N_NODES * HC];

// ---------------- f32x2 helpers -------------------------------------------------
__device__ __forceinline__ unsigned long long pk2(float lo, float hi) {
    unsigned long long r;
    asm("mov.b64 %0, {%1,%2};" : "=l"(r) : "f"(lo), "f"(hi));
    return r;
}
__device__ __forceinline__ void fma2(unsigned long long& d,
                                     unsigned long long a,
                                     unsigned long long b) {
    asm("fma.rn.f32x2 %0, %1, %2, %0;" : "+l"(d) : "l"(a), "l"(b));
}
__device__ __forceinline__ void unpk2(float& lo, float& hi, unsigned long long v) {
    asm("mov.b64 {%0,%1}, %2;" : "=f"(lo), "=f"(hi) : "l"(v));
}
__device__ __forceinline__ float hsum2(unsigned long long v) {
    float lo, hi; unpk2(lo, hi, v); return lo + hi;
}

// ---------------- K: zero degree histogram --------------------------------------
__global__ void k_zero() {
    int i = blockIdx.x * blockDim.x + threadIdx.x;
    if (i < N_NODES) g_deg[i] = 0;
}

// ---------------- K: degree histogram -------------------------------------------
__global__ void k_deg(const int* __restrict__ ei) {
    int e = blockIdx.x * blockDim.x + threadIdx.x;
    if (e < N_EDGES) atomicAdd(&g_deg[ei[N_EDGES + e]], 1);
}

// ---------------- K: fold attention vectors -------------------------------------
__global__ void k_fold(const float* __restrict__ Wn, const float* __restrict__ We,
                       const float* __restrict__ att) {
    int t = threadIdx.x;
    if (t < 48) {
        int h = t >> 4, k = t & 15;
        float s = 0.f;
        const float* wr = We + k * HC + h * 64;
        const float* ar = att + h * HC + 64;
#pragma unroll 8
        for (int c = 0; c < 64; c++) s += wr[c] * ar[c];
        g_q[t] = s;
    } else if (t < 48 + 384) {
        int o2 = t - 48;
        int o = o2 >> 6, k = o2 & 63;
        int type = (o >= 3), h = (o >= 3) ? o - 3 : o;
        float s = 0.f;
        const float* wr = Wn + k * HC + h * 64;
        const float* ar = att + h * HC + type * 128;
#pragma unroll 8
        for (int c = 0; c < 64; c++) s += wr[c] * ar[c];
        g_v[o * 64 + k] = s;
    }
}

// ---------------- K: x_proj (fp16) + shuffle-free s0/s2 — 16 nodes/block --------
__global__ void k_projs(const float* __restrict__ x, const float* __restrict__ Wn) {
    __shared__ __align__(16) float xT[64 * 16];  // [k][n]
    __shared__ float s_v[6 * 65];
    int n0 = blockIdx.x * 16;
    int t = threadIdx.x;                 // 0..95
    int ch0 = t, ch1 = t + 96;
    for (int i = t; i < 16 * 64; i += 96) {
        int n = i >> 6, k = i & 63;
        xT[k * 16 + n] = x[(n0 + n) * 64 + k];
    }
    for (int i = t; i < 384; i += 96) {
        int o = i >> 6, k = i & 63;
        s_v[o * 65 + k] = g_v[i];
    }
    __syncthreads();
    unsigned long long accA2[8], accB2[8];
#pragma unroll
    for (int p = 0; p < 8; p++) { accA2[p] = 0ull; accB2[p] = 0ull; }
#pragma unroll 4
    for (int k = 0; k < 64; k++) {
        float wa = Wn[k * HC + ch0];
        float wb = Wn[k * HC + ch1];
        unsigned long long wa2 = pk2(wa, wa), wb2 = pk2(wb, wb);
        const ulonglong2* xr = reinterpret_cast<const ulonglong2*>(xT + k * 16);
        ulonglong2 q0 = xr[0], q1 = xr[1], q2 = xr[2], q3 = xr[3];
        fma2(accA2[0], q0.x, wa2); fma2(accA2[1], q0.y, wa2);
        fma2(accA2[2], q1.x, wa2); fma2(accA2[3], q1.y, wa2);
        fma2(accA2[4], q2.x, wa2); fma2(accA2[5], q2.y, wa2);
        fma2(accA2[6], q3.x, wa2); fma2(accA2[7], q3.y, wa2);
        fma2(accB2[0], q0.x, wb2); fma2(accB2[1], q0.y, wb2);
        fma2(accB2[2], q1.x, wb2); fma2(accB2[3], q1.y, wb2);
        fma2(accB2[4], q2.x, wb2); fma2(accB2[5], q2.y, wb2);
        fma2(accB2[6], q3.x, wb2); fma2(accB2[7], q3.y, wb2);
    }
    float accA[16], accB[16];
#pragma unroll
    for (int p = 0; p < 8; p++) {
        unpk2(accA[2 * p], accA[2 * p + 1], accA2[p]);
        unpk2(accB[2 * p], accB[2 * p + 1], accB2[p]);
    }
#pragma unroll
    for (int n = 0; n < 16; n++) {
        g_xh[(n0 + n) * HC + ch0] = __float2half(accA[n]);
        g_xh[(n0 + n) * HC + ch1] = __float2half(accB[n]);
    }

    // shuffle-free s0/s2: 96 dots of length 64 (o = type*3+h, n = node)
    {
        int n = t & 15, o = t >> 4;          // o in [0,6)
        int type = (o >= 3), h = (o >= 3) ? o - 3 : o;
        const float* vv = s_v + o * 65;
        float s = 0.f;
#pragma unroll 8
        for (int k = 0; k < 64; k++) s += xT[k * 16 + n] * vv[k];
        g_sn[(n0 + n) * 8 + type * 4 + h] = s;
    }
}

// ---------------- K: scan phase 1 ------------------------------------------------
__global__ void k_scan1() {
    __shared__ int s_ws[32], s_off[32];
    int t = threadIdx.x, w = t >> 5, lane = t & 31;
    int i = blockIdx.x * 1024 + t;
    int v = (i < N_NODES) ? g_deg[i] : 0;
    int incl = v;
#pragma unroll
    for (int o = 1; o < 32; o <<= 1) {
        int u = __shfl_up_sync(0xffffffffu, incl, o);
        if (lane >= o) incl += u;
    }
    if (lane == 31) s_ws[w] = incl;
    __syncthreads();
    if (w == 0) {
        int wv = s_ws[lane];
        int inc2 = wv;
#pragma unroll
        for (int o = 1; o < 32; o <<= 1) {
            int u = __shfl_up_sync(0xffffffffu, inc2, o);
            if (lane >= o) inc2 += u;
        }
        s_off[lane] = inc2 - wv;
        if (lane == 31) g_tsum[blockIdx.x] = inc2;
    }
    __syncthreads();
    if (i < N_NODES) g_rowptr[i] = s_off[w] + incl - v;
}

// ---------------- K: scan phase 2 -------------------------------------------------
__global__ void k_scan2() {
    __shared__ int s[64];
    int t = threadIdx.x;
    int v = (t < NTILES) ? g_tsum[t] : 0;
    s[t] = v;
    __syncthreads();
#pragma unroll
    for (int o = 1; o < 64; o <<= 1) {
        int add = (t >= o) ? s[t - o] : 0;
        __syncthreads();
        s[t] += add;
        __syncthreads();
    }
    if (t < NTILES) g_toff[t] = s[t] - v;
    if (t == NTILES - 1) g_rowptr[N_NODES] = s[t];
}

// ---------------- K: scan phase 3 -------------------------------------------------
__global__ void k_scan3() {
    int i = blockIdx.x * 1024 + threadIdx.x;
    if (i < N_NODES) {
        int v = g_rowptr[i] + g_toff[blockIdx.x];
        g_rowptr[i] = v;
        g_cursor[i] = v;
    }
}

// ---------------- K: light CSR scatter of (src, eid) ------------------------------
__global__ void k_scatter(const int* __restrict__ ei) {
    int e = blockIdx.x * blockDim.x + threadIdx.x;
    if (e >= N_EDGES) return;
    int src = ei[e];
    int dst = ei[N_EDGES + e];
    int pos = atomicAdd(&g_cursor[dst], 1);
    g_se[pos] = make_int2(src, e);
}

// ---------------- K: per-node aggregation with in-block alpha (R9 proven) --------
// One node per block. 96 threads: thread t owns channels (2t,2t+1); h = t>>5.
#define CHUNK 32
__global__ void __launch_bounds__(96) k_aggr(const float* __restrict__ eattr,
                                             const float* __restrict__ We) {
    int t = threadIdx.x;
    int c0 = 2 * t;
    int h = t >> 5;
    int ae = t & 31;

    unsigned long long Wp0[8], Wp1[8];
#pragma unroll
    for (int m = 0; m < 8; m++) {
        Wp0[m] = pk2(We[(2 * m) * HC + c0],     We[(2 * m + 1) * HC + c0]);
        Wp1[m] = pk2(We[(2 * m) * HC + c0 + 1], We[(2 * m + 1) * HC + c0 + 1]);
    }

    __shared__ float qs[48];
    __shared__ float s_w[3 * CHUNK];
    __shared__ int   s_src[CHUNK];
    __shared__ __align__(16) float4 s_sn2[CHUNK];
    __shared__ __align__(16) float  s_ea[CHUNK * 16];
    if (t < 48) qs[t] = g_q[t];

    int i = blockIdx.x;
    int rs = g_rowptr[i], re = g_rowptr[i + 1];
    float sb = g_sn[(size_t)i * 8 + h];      // dst s0 for my head (warp-uniform)
    float z = 0.f;
    unsigned long long acc0 = 0ull, acc1 = 0ull;

    for (int base = rs; base < re; base += CHUNK) {
        int Cn = min(CHUNK, re - base);
        if (t < Cn) {
            int2 se = g_se[base + t];
            s_src[t] = se.x;
            s_sn2[t] = *reinterpret_cast<const float4*>(g_sn + (size_t)se.x * 8 + 4);
        }
        // eattr gather spread across all 96 threads (4 float4 per edge)
        for (int u = t; u < Cn * 4; u += 96) {
            int edge = u >> 2, part = u & 3;
            int eid = g_se[base + edge].y;
            reinterpret_cast<float4*>(s_ea)[u] =
                reinterpret_cast<const float4*>(eattr)[(size_t)eid * 4 + part];
        }
        __syncthreads();

        // alpha for (edge ae, head h): 16-dot + leaky + exp
        if (ae < Cn) {
            const float* q = qs + h * 16;
            const float4* er = reinterpret_cast<const float4*>(s_ea + ae * 16);
            float4 b0 = er[0], b1 = er[1], b2 = er[2], b3 = er[3];
            float s = sb + reinterpret_cast<const float*>(&s_sn2[ae])[h];
            s += b0.x * q[0]  + b0.y * q[1]  + b0.z * q[2]  + b0.w * q[3];
            s += b1.x * q[4]  + b1.y * q[5]  + b1.z * q[6]  + b1.w * q[7];
            s += b2.x * q[8]  + b2.y * q[9]  + b2.z * q[10] + b2.w * q[11];
            s += b3.x * q[12] + b3.y * q[13] + b3.z * q[14] + b3.w * q[15];
            s = (s >= 0.f) ? s : NEG_SLOPE * s;
            s_w[h * CHUNK + ae] = __expf(s);
        }
        __syncwarp();   // s_w: writer lane == reader warp

        int srcc = s_src[0];
        __half2 xh = *reinterpret_cast<const __half2*>(
            g_xh + (size_t)srcc * HC + c0);
        for (int j = 0; j < Cn; j++) {
            __half2 xhn;
            if (j + 1 < Cn) {
                int srcn = s_src[j + 1];
                xhn = *reinterpret_cast<const __half2*>(
                    g_xh + (size_t)srcn * HC + c0);
            }
            float2 xj = __half22float2(xh);
            const ulonglong2* eap =
                reinterpret_cast<const ulonglong2*>(s_ea + j * 16);
            ulonglong2 p0 = eap[0], p1 = eap[1], p2 = eap[2], p3 = eap[3];
            unsigned long long e0 = 0ull, e1 = 0ull;
            fma2(e0, p0.x, Wp0[0]); fma2(e1, p0.x, Wp1[0]);
            fma2(e0, p0.y, Wp0[1]); fma2(e1, p0.y, Wp1[1]);
            fma2(e0, p1.x, Wp0[2]); fma2(e1, p1.x, Wp1[2]);
            fma2(e0, p1.y, Wp0[3]); fma2(e1, p1.y, Wp1[3]);
            fma2(e0, p2.x, Wp0[4]); fma2(e1, p2.x, Wp1[4]);
            fma2(e0, p2.y, Wp0[5]); fma2(e1, p2.y, Wp1[5]);
            fma2(e0, p3.x, Wp0[6]); fma2(e1, p3.x, Wp1[6]);
            fma2(e0, p3.y, Wp0[7]); fma2(e1, p3.y, Wp1[7]);
            float w = s_w[h * CHUNK + j];
            z += w;
            float wx0 = w * xj.x, wx1 = w * xj.y;
            fma2(acc0, e0, pk2(wx0, wx0));
            fma2(acc1, e1, pk2(wx1, wx1));
            xh = xhn;
        }
        __syncthreads();
    }
    float inv = 1.f / (z + 1e-16f);
    *reinterpret_cast<float2*>(g_aggr + (size_t)i * HC + c0) =
        make_float2(hsum2(acc0) * inv, hsum2(acc1) * inv);
}

// ---------------- K: out = aggr @ W_scale + bias — 16 nodes/block ----------------
__global__ void k_out(const float* __restrict__ Ws, const float* __restrict__ bias,
                      float* __restrict__ out) {
    __shared__ __align__(16) float aT[HC * 16];  // [k][n]
    int n0 = blockIdx.x * 16;
    int t = threadIdx.x;  // 0..63
    for (int i = t; i < 16 * HC; i += 64) {
        int n = i / HC, k = i - n * HC;
        aT[k * 16 + n] = g_aggr[(n0 + n) * HC + k];
    }
    __syncthreads();
    unsigned long long acc2[8];
#pragma unroll
    for (int p = 0; p < 8; p++) acc2[p] = 0ull;
#pragma unroll 4
    for (int k = 0; k < HC; k++) {
        unsigned long long wv2 = pk2(Ws[k * 64 + t], Ws[k * 64 + t]);
        const ulonglong2* ar = reinterpret_cast<const ulonglong2*>(aT + k * 16);
        ulonglong2 q0 = ar[0], q1 = ar[1], q2 = ar[2], q3 = ar[3];
        fma2(acc2[0], q0.x, wv2); fma2(acc2[1], q0.y, wv2);
        fma2(acc2[2], q1.x, wv2); fma2(acc2[3], q1.y, wv2);
        fma2(acc2[4], q2.x, wv2); fma2(acc2[5], q2.y, wv2);
        fma2(acc2[6], q3.x, wv2); fma2(acc2[7], q3.y, wv2);
    }
    float acc[16];
#pragma unroll
    for (int p = 0; p < 8; p++) unpk2(acc[2 * p], acc[2 * p + 1], acc2[p]);
    float b = bias[t];
#pragma unroll
    for (int n = 0; n < 16; n++) out[(n0 + n) * 64 + t] = acc[n] + b;
}

// ---------------- launch ----------------------------------------------------------
extern "C" void kernel_launch(void* const* d_in, const int* in_sizes, int n_in,
                              void* d_out, int out_size) {
    const float* x     = (const float*)d_in[0];
    const int*   ei    = (const int*)d_in[1];
    const float* eattr = (const float*)d_in[2];
    const float* Wn    = (const float*)d_in[3];
    const float* We    = (const float*)d_in[4];
    const float* att   = (const float*)d_in[5];
    const float* Ws    = (const float*)d_in[6];
    const float* bias  = (const float*)d_in[7];
    float*       out   = (float*)d_out;

    k_zero<<<(N_NODES + 255) / 256, 256>>>();
    k_deg<<<(N_EDGES + 255) / 256, 256>>>(ei);
    k_fold<<<1, 448>>>(Wn, We, att);
    k_projs<<<N_NODES / 16, 96>>>(x, Wn);   // 4th launch -> profiled
    k_scan1<<<NTILES, 1024>>>();
    k_scan2<<<1, 64>>>();
    k_scan3<<<NTILES, 1024>>>();
    k_scatter<<<(N_EDGES + 255) / 256, 256>>>(ei);
    k_aggr<<<N_NODES, 96>>>(eattr, We);
    k_out<<<N_NODES / 16, 64>>>(Ws, bias, out);
}